// round 4
// baseline (speedup 1.0000x reference)
#include <cuda_runtime.h>
#include <math.h>

// Shapes (fixed by the problem)
//  x       [16][16][4096]
//  conv_w  [256][16][9]
//  conv_b  [256]
//  caps_w  [8][16][256]
//  caps_b  [8][16]
//  W       [8][16][16]
//  out     [8][16][8][4096]  (n0, k, n, s)
//
// Algebra:
//  u[b,k,n,s]   = Weff[n,k] (*) x[b] + beff[n,k]          (Weff = caps_w · conv_w)
//  s0[n0,k,n,s] = Weff[n,k] (*) xc[n0,k] + beff           (xc = Σ_b C[n0,k,b]·x[b], ΣC=1)
//  U[k,n,s]     = Weff[n,k] (*) xU + 16·beff              (xU = Σ_b x[b])
//  s1 = s0·(1 + f0·s0·U); s2 = s0 + f1·s1²·U; out = f2·s2; f(SS)=√SS/(1+SS), SS=Σ_s s²

__device__ float g_C[128 * 16];          // [n0*16+k][b]
__device__ float g_Weff[128 * 144];      // [n*16+k][ic*9+dk]
__device__ float g_beff[128];            // [n*16+k]
__device__ float g_xc[128 * 16 * 4096];  // [n0*16+k][ic][s]   (32 MB)
__device__ float g_xU[16 * 4096];        // [ic][s]
__device__ float g_U[128 * 4096];        // [k*8+n][s]          (2 MB)
__device__ float g_s0[1024 * 4096];      // [n0*128+k*8+n][s]   (16 MB)

// ---------------------------------------------------------------------------
// K0: softmax rows of W (over b axis) and effective bias
// ---------------------------------------------------------------------------
__global__ void k_setup(const float* __restrict__ Wr,
                        const float* __restrict__ caps_w,
                        const float* __restrict__ conv_b,
                        const float* __restrict__ caps_b) {
    int t = threadIdx.x;
    if (t < 128) {
        int n0 = t >> 4, k = t & 15;
        float m = -1e30f;
        float e[16];
        #pragma unroll
        for (int b = 0; b < 16; b++)
            m = fmaxf(m, Wr[(n0 * 16 + b) * 16 + k]);
        float sum = 0.f;
        #pragma unroll
        for (int b = 0; b < 16; b++) {
            float v = expf(Wr[(n0 * 16 + b) * 16 + k] - m);
            e[b] = v;
            sum += v;
        }
        float inv = 1.f / sum;
        #pragma unroll
        for (int b = 0; b < 16; b++)
            g_C[(n0 * 16 + k) * 16 + b] = e[b] * inv;

        // beff[nk] = sum_oc caps_w[nk][oc] * conv_b[oc] + caps_b[nk]
        float acc = caps_b[t];
        for (int oc = 0; oc < 256; oc++)
            acc += caps_w[t * 256 + oc] * conv_b[oc];
        g_beff[t] = acc;
    }
}

// ---------------------------------------------------------------------------
// K0b: Weff[nk][ic*9+dk] = sum_oc caps_w[nk][oc] * conv_w[oc][ic][dk]
// ---------------------------------------------------------------------------
__global__ void k_weff(const float* __restrict__ caps_w,
                       const float* __restrict__ conv_w) {
    int nk = blockIdx.x;
    __shared__ float cw[256];
    for (int i = threadIdx.x; i < 256; i += blockDim.x)
        cw[i] = caps_w[nk * 256 + i];
    __syncthreads();
    int t = threadIdx.x;
    if (t < 144) {
        int ic = t / 9, dk = t - ic * 9;
        float acc = 0.f;
        for (int oc = 0; oc < 256; oc++)
            acc += cw[oc] * conv_w[(oc * 16 + ic) * 9 + dk];
        g_Weff[nk * 144 + t] = acc;
    }
}

// ---------------------------------------------------------------------------
// K1: xc[n0k][ic][s] = sum_b C[n0k][b] * x[b][ic][s];  xU[ic][s] = sum_b x
// grid (ic=16, stile=8 of 512); 128 threads, 4 s per thread
// ---------------------------------------------------------------------------
__global__ __launch_bounds__(128) void k_xc(const float* __restrict__ x) {
    const int ic = blockIdx.x;
    const int sbase = blockIdx.y * 512;
    const int tid = threadIdx.x;

    __shared__ __align__(16) float xs[16][512];
    __shared__ float Cs[128][16];

    for (int idx = tid; idx < 16 * 128; idx += 128) {
        int b = idx >> 7, q = idx & 127;
        float4 v = *reinterpret_cast<const float4*>(&x[(b * 16 + ic) * 4096 + sbase + q * 4]);
        *reinterpret_cast<float4*>(&xs[b][q * 4]) = v;
    }
    for (int idx = tid; idx < 2048; idx += 128)
        Cs[idx >> 4][idx & 15] = g_C[idx];
    __syncthreads();

    float xb[16][4];
    #pragma unroll
    for (int b = 0; b < 16; b++) {
        float4 v = *reinterpret_cast<const float4*>(&xs[b][tid * 4]);
        xb[b][0] = v.x; xb[b][1] = v.y; xb[b][2] = v.z; xb[b][3] = v.w;
    }

    // xU
    {
        float u0 = 0.f, u1 = 0.f, u2 = 0.f, u3 = 0.f;
        #pragma unroll
        for (int b = 0; b < 16; b++) {
            u0 += xb[b][0]; u1 += xb[b][1]; u2 += xb[b][2]; u3 += xb[b][3];
        }
        *reinterpret_cast<float4*>(&g_xU[ic * 4096 + sbase + tid * 4]) =
            make_float4(u0, u1, u2, u3);
    }

    for (int nk = 0; nk < 128; nk++) {
        float a0 = 0.f, a1 = 0.f, a2 = 0.f, a3 = 0.f;
        #pragma unroll
        for (int b = 0; b < 16; b++) {
            float c = Cs[nk][b];
            a0 = fmaf(c, xb[b][0], a0);
            a1 = fmaf(c, xb[b][1], a1);
            a2 = fmaf(c, xb[b][2], a2);
            a3 = fmaf(c, xb[b][3], a3);
        }
        *reinterpret_cast<float4*>(&g_xc[(nk * 16 + ic) * 4096 + sbase + tid * 4]) =
            make_float4(a0, a1, a2, a3);
    }
}

// ---------------------------------------------------------------------------
// K2: U[k*8+n][s] = Weff[n*16+k] (*) xU + 16*beff.  grid 128 (kn2), 128 thr
// ---------------------------------------------------------------------------
__global__ __launch_bounds__(128) void k_ucalc() {
    const int kn2 = blockIdx.x;            // k*8+n
    const int k = kn2 >> 3, n = kn2 & 7;
    const int nk = n * 16 + k;
    const int tid = threadIdx.x;

    __shared__ __align__(16) float xt[16][264];

    float w[144];
    #pragma unroll
    for (int i = 0; i < 144; i++) w[i] = g_Weff[nk * 144 + i];
    const float bias = 16.f * g_beff[nk];

    for (int c = 0; c < 16; c++) {
        const int sc = c * 256;
        __syncthreads();
        for (int j = tid; j < 16 * 264; j += 128) {
            int ic = j / 264, jj = j - ic * 264;
            int s = sc - 4 + jj;
            xt[ic][jj] = (s >= 0 && s < 4096) ? g_xU[ic * 4096 + s] : 0.f;
        }
        __syncthreads();

        const int sb = tid * 2;
        float a0 = bias, a1 = bias;
        #pragma unroll
        for (int ic = 0; ic < 16; ic++) {
            float xv[10];
            #pragma unroll
            for (int q = 0; q < 5; q++) {
                float2 v = *reinterpret_cast<const float2*>(&xt[ic][sb + q * 2]);
                xv[q * 2] = v.x; xv[q * 2 + 1] = v.y;
            }
            #pragma unroll
            for (int dk = 0; dk < 9; dk++) {
                float wv = w[ic * 9 + dk];
                a0 = fmaf(wv, xv[dk], a0);
                a1 = fmaf(wv, xv[dk + 1], a1);
            }
        }
        *reinterpret_cast<float2*>(&g_U[kn2 * 4096 + sc + sb]) = make_float2(a0, a1);
    }
}

// ---------------------------------------------------------------------------
// K3: s0[n0,k,n][s] = Weff[n*16+k] (*) xc[n0*16+k] + beff
// grid (stile=16 of 256, n0k=128); 128 threads = n(tid&7) x g(tid>>3)
// lane phases of 8 share g -> LDS broadcast, conflict-free
// ---------------------------------------------------------------------------
__global__ __launch_bounds__(128) void k_s0conv() {
    const int sc = blockIdx.x * 256;
    const int n0k = blockIdx.y;            // n0*16 + k
    const int k = n0k & 15;
    const int tid = threadIdx.x;
    const int n = tid & 7;
    const int g = tid >> 3;                // 0..15
    const int nk = n * 16 + k;

    __shared__ __align__(16) float xt[16][264];

    for (int j = tid; j < 16 * 264; j += 128) {
        int ic = j / 264, jj = j - ic * 264;
        int s = sc - 4 + jj;
        xt[ic][jj] = (s >= 0 && s < 4096) ? g_xc[(n0k * 16 + ic) * 4096 + s] : 0.f;
    }

    float w[144];
    #pragma unroll
    for (int i = 0; i < 144; i++) w[i] = g_Weff[nk * 144 + i];
    const float bv = g_beff[nk];
    __syncthreads();

    float acc[16];
    #pragma unroll
    for (int t = 0; t < 16; t++) acc[t] = bv;
    const int sb = g * 16;

    #pragma unroll
    for (int ic = 0; ic < 16; ic++) {
        float xv[24];
        #pragma unroll
        for (int q = 0; q < 6; q++) {
            float4 v = *reinterpret_cast<const float4*>(&xt[ic][sb + q * 4]);
            xv[q * 4 + 0] = v.x; xv[q * 4 + 1] = v.y;
            xv[q * 4 + 2] = v.z; xv[q * 4 + 3] = v.w;
        }
        #pragma unroll
        for (int dk = 0; dk < 9; dk++) {
            float wv = w[ic * 9 + dk];
            #pragma unroll
            for (int t = 0; t < 16; t++)
                acc[t] = fmaf(wv, xv[t + dk], acc[t]);
        }
    }

    float* orow = &g_s0[(((n0k >> 4) * 128) + k * 8 + n) * 4096 + sc + sb];
    #pragma unroll
    for (int q = 0; q < 4; q++)
        *reinterpret_cast<float4*>(&orow[q * 4]) =
            make_float4(acc[q * 4], acc[q * 4 + 1], acc[q * 4 + 2], acc[q * 4 + 3]);
}

// ---------------------------------------------------------------------------
// K4: squash iterations. one block per (n0,k,n) = bid; reads s0 row + U row.
// ---------------------------------------------------------------------------
__device__ __forceinline__ float block_reduce(float p, float* red, int tid) {
    #pragma unroll
    for (int o = 16; o > 0; o >>= 1)
        p += __shfl_xor_sync(0xffffffffu, p, o);
    __syncthreads();
    if ((tid & 31) == 0) red[tid >> 5] = p;
    __syncthreads();
    if (tid == 0) {
        float s = 0.f;
        #pragma unroll
        for (int i = 0; i < 8; i++) s += red[i];
        red[8] = s;
    }
    __syncthreads();
    return red[8];
}

__global__ __launch_bounds__(256) void k_squash(float* __restrict__ out) {
    const int bid = blockIdx.x;            // n0*128 + k*8 + n
    const int kn2 = bid & 127;             // k*8+n
    const int tid = threadIdx.x;

    __shared__ __align__(16) float s0s[4096];
    __shared__ __align__(16) float Us[4096];
    __shared__ float red[9];

    const float4* s0g = reinterpret_cast<const float4*>(&g_s0[bid * 4096]);
    const float4* Ug  = reinterpret_cast<const float4*>(&g_U[kn2 * 4096]);
    for (int i = tid; i < 1024; i += 256) {
        *reinterpret_cast<float4*>(&s0s[i * 4]) = s0g[i];
        *reinterpret_cast<float4*>(&Us[i * 4])  = Ug[i];
    }
    __syncthreads();

    float p, SS;

    // SS0
    p = 0.f;
    for (int s = tid; s < 4096; s += 256) { float v = s0s[s]; p = fmaf(v, v, p); }
    SS = block_reduce(p, red, tid);
    const float f0 = sqrtf(SS) / (1.f + SS);

    // SS1
    p = 0.f;
    for (int s = tid; s < 4096; s += 256) {
        float a = s0s[s], Uv = Us[s];
        float s1 = a * (1.f + f0 * a * Uv);
        p = fmaf(s1, s1, p);
    }
    SS = block_reduce(p, red, tid);
    const float f1 = sqrtf(SS) / (1.f + SS);

    // SS2
    p = 0.f;
    for (int s = tid; s < 4096; s += 256) {
        float a = s0s[s], Uv = Us[s];
        float s1 = a * (1.f + f0 * a * Uv);
        float s2 = a + f1 * s1 * s1 * Uv;
        p = fmaf(s2, s2, p);
    }
    SS = block_reduce(p, red, tid);
    const float f2 = sqrtf(SS) / (1.f + SS);

    float* orow = out + bid * 4096;
    for (int s = tid; s < 4096; s += 256) {
        float a = s0s[s], Uv = Us[s];
        float s1 = a * (1.f + f0 * a * Uv);
        float s2 = a + f1 * s1 * s1 * Uv;
        orow[s] = f2 * s2;
    }
}

// ---------------------------------------------------------------------------
extern "C" void kernel_launch(void* const* d_in, const int* in_sizes, int n_in,
                              void* d_out, int out_size) {
    const float* x      = (const float*)d_in[0];
    const float* conv_w = (const float*)d_in[1];
    const float* conv_b = (const float*)d_in[2];
    const float* caps_w = (const float*)d_in[3];
    const float* caps_b = (const float*)d_in[4];
    const float* W      = (const float*)d_in[5];
    float* out = (float*)d_out;

    k_setup<<<1, 128>>>(W, caps_w, conv_b, caps_b);
    k_weff<<<128, 160>>>(caps_w, conv_w);
    k_xc<<<dim3(16, 8), 128>>>(x);
    k_ucalc<<<128, 128>>>();
    k_s0conv<<<dim3(16, 128), 128>>>();
    k_squash<<<1024, 256>>>(out);
}

// round 5
// speedup vs baseline: 1.3092x; 1.3092x over previous
#include <cuda_runtime.h>
#include <math.h>

// Shapes (fixed by the problem)
//  x       [16][16][4096]
//  conv_w  [256][16][9]
//  conv_b  [256]
//  caps_w  [8][16][256]
//  caps_b  [8][16]
//  W       [8][16][16]
//  out     [8][16][8][4096]  (n0, k, n, s)
//
// Algebra:
//  s0[n0,k,n,s] = Weff[n,k] (*) xc[n0,k] + beff           (xc = Σ_b C[n0,k,b]·x[b], ΣC=1)
//  U[k,n,s]     = Weff[n,k] (*) xU + 16·beff              (xU = Σ_b x[b])
//  s1 = s0·(1 + f0·s0·U); s2 = s0 + f1·s1²·U; out = f2·s2; f(SS)=√SS/(1+SS), SS=Σ_s s²

__device__ float g_C[128 * 16];          // [n0*16+k][b]
__device__ float g_Weff[128 * 144];      // [n*16+k][ic*9+dk]
__device__ float g_beff[128];            // [n*16+k]
__device__ float g_xc[128 * 16 * 4096];  // [n0*16+k][ic][s]   (32 MB)
__device__ float g_xU[16 * 4096];        // [ic][s]
__device__ float g_U[128 * 4096];        // [k*8+n][s]          (2 MB)
__device__ float g_s0[1024 * 4096];      // [n0*128+k*8+n][s]   (16 MB)

// ---------------------------------------------------------------------------
// K0: softmax rows of W (over b axis) and effective bias
// ---------------------------------------------------------------------------
__global__ void k_setup(const float* __restrict__ Wr,
                        const float* __restrict__ caps_w,
                        const float* __restrict__ conv_b,
                        const float* __restrict__ caps_b) {
    int t = threadIdx.x;
    if (t < 128) {
        int n0 = t >> 4, k = t & 15;
        float m = -1e30f;
        float e[16];
        #pragma unroll
        for (int b = 0; b < 16; b++)
            m = fmaxf(m, Wr[(n0 * 16 + b) * 16 + k]);
        float sum = 0.f;
        #pragma unroll
        for (int b = 0; b < 16; b++) {
            float v = expf(Wr[(n0 * 16 + b) * 16 + k] - m);
            e[b] = v;
            sum += v;
        }
        float inv = 1.f / sum;
        #pragma unroll
        for (int b = 0; b < 16; b++)
            g_C[(n0 * 16 + k) * 16 + b] = e[b] * inv;

        // beff[nk] = sum_oc caps_w[nk][oc] * conv_b[oc] + caps_b[nk]
        float acc = caps_b[t];
        for (int oc = 0; oc < 256; oc++)
            acc += caps_w[t * 256 + oc] * conv_b[oc];
        g_beff[t] = acc;
    }
}

// ---------------------------------------------------------------------------
// K0b: Weff[nk][ic*9+dk] = sum_oc caps_w[nk][oc] * conv_w[oc][ic][dk]
// ---------------------------------------------------------------------------
__global__ void k_weff(const float* __restrict__ caps_w,
                       const float* __restrict__ conv_w) {
    int nk = blockIdx.x;
    __shared__ float cw[256];
    for (int i = threadIdx.x; i < 256; i += blockDim.x)
        cw[i] = caps_w[nk * 256 + i];
    __syncthreads();
    int t = threadIdx.x;
    if (t < 144) {
        int ic = t / 9, dk = t - ic * 9;
        float acc = 0.f;
        for (int oc = 0; oc < 256; oc++)
            acc += cw[oc] * conv_w[(oc * 16 + ic) * 9 + dk];
        g_Weff[nk * 144 + t] = acc;
    }
}

// ---------------------------------------------------------------------------
// K1: xc[n0k][ic][s] = sum_b C[n0k][b] * x[b][ic][s];  xU[ic][s] = sum_b x
// grid (ic=16, stile=8 of 512); 128 threads, 4 s per thread
// ---------------------------------------------------------------------------
__global__ __launch_bounds__(128) void k_xc(const float* __restrict__ x) {
    const int ic = blockIdx.x;
    const int sbase = blockIdx.y * 512;
    const int tid = threadIdx.x;

    __shared__ __align__(16) float xs[16][512];
    __shared__ float Cs[128][16];

    for (int idx = tid; idx < 16 * 128; idx += 128) {
        int b = idx >> 7, q = idx & 127;
        float4 v = *reinterpret_cast<const float4*>(&x[(b * 16 + ic) * 4096 + sbase + q * 4]);
        *reinterpret_cast<float4*>(&xs[b][q * 4]) = v;
    }
    for (int idx = tid; idx < 2048; idx += 128)
        Cs[idx >> 4][idx & 15] = g_C[idx];
    __syncthreads();

    float xb[16][4];
    #pragma unroll
    for (int b = 0; b < 16; b++) {
        float4 v = *reinterpret_cast<const float4*>(&xs[b][tid * 4]);
        xb[b][0] = v.x; xb[b][1] = v.y; xb[b][2] = v.z; xb[b][3] = v.w;
    }

    // xU
    {
        float u0 = 0.f, u1 = 0.f, u2 = 0.f, u3 = 0.f;
        #pragma unroll
        for (int b = 0; b < 16; b++) {
            u0 += xb[b][0]; u1 += xb[b][1]; u2 += xb[b][2]; u3 += xb[b][3];
        }
        *reinterpret_cast<float4*>(&g_xU[ic * 4096 + sbase + tid * 4]) =
            make_float4(u0, u1, u2, u3);
    }

    for (int nk = 0; nk < 128; nk++) {
        float a0 = 0.f, a1 = 0.f, a2 = 0.f, a3 = 0.f;
        #pragma unroll
        for (int b = 0; b < 16; b++) {
            float c = Cs[nk][b];
            a0 = fmaf(c, xb[b][0], a0);
            a1 = fmaf(c, xb[b][1], a1);
            a2 = fmaf(c, xb[b][2], a2);
            a3 = fmaf(c, xb[b][3], a3);
        }
        *reinterpret_cast<float4*>(&g_xc[(nk * 16 + ic) * 4096 + sbase + tid * 4]) =
            make_float4(a0, a1, a2, a3);
    }
}

// ---------------------------------------------------------------------------
// K2: U[k*8+n][s] = Weff[n*16+k] (*) xU + 16*beff
// grid (stile=16 of 256, k=16); 128 threads = n(tid&7) x g(tid>>3)
// same structure as k_s0conv (proven FFMA-bound shape)
// ---------------------------------------------------------------------------
__global__ __launch_bounds__(128) void k_ucalc() {
    const int sc = blockIdx.x * 256;
    const int k  = blockIdx.y;
    const int tid = threadIdx.x;
    const int n = tid & 7;
    const int g = tid >> 3;                // 0..15
    const int nk = n * 16 + k;

    __shared__ __align__(16) float xt[16][264];

    for (int j = tid; j < 16 * 264; j += 128) {
        int ic = j / 264, jj = j - ic * 264;
        int s = sc - 4 + jj;
        xt[ic][jj] = (s >= 0 && s < 4096) ? g_xU[ic * 4096 + s] : 0.f;
    }

    float w[144];
    #pragma unroll
    for (int i = 0; i < 144; i++) w[i] = g_Weff[nk * 144 + i];
    const float bv = 16.f * g_beff[nk];
    __syncthreads();

    float acc[16];
    #pragma unroll
    for (int t = 0; t < 16; t++) acc[t] = bv;
    const int sb = g * 16;

    #pragma unroll
    for (int ic = 0; ic < 16; ic++) {
        float xv[24];
        #pragma unroll
        for (int q = 0; q < 6; q++) {
            float4 v = *reinterpret_cast<const float4*>(&xt[ic][sb + q * 4]);
            xv[q * 4 + 0] = v.x; xv[q * 4 + 1] = v.y;
            xv[q * 4 + 2] = v.z; xv[q * 4 + 3] = v.w;
        }
        #pragma unroll
        for (int dk = 0; dk < 9; dk++) {
            float wv = w[ic * 9 + dk];
            #pragma unroll
            for (int t = 0; t < 16; t++)
                acc[t] = fmaf(wv, xv[t + dk], acc[t]);
        }
    }

    float* orow = &g_U[(k * 8 + n) * 4096 + sc + sb];
    #pragma unroll
    for (int q = 0; q < 4; q++)
        *reinterpret_cast<float4*>(&orow[q * 4]) =
            make_float4(acc[q * 4], acc[q * 4 + 1], acc[q * 4 + 2], acc[q * 4 + 3]);
}

// ---------------------------------------------------------------------------
// K3: s0[n0,k,n][s] = Weff[n*16+k] (*) xc[n0*16+k] + beff
// grid (stile=16 of 256, n0k=128); 128 threads = n(tid&7) x g(tid>>3)
// lane phases of 8 share g -> LDS broadcast, conflict-free
// ---------------------------------------------------------------------------
__global__ __launch_bounds__(128) void k_s0conv() {
    const int sc = blockIdx.x * 256;
    const int n0k = blockIdx.y;            // n0*16 + k
    const int k = n0k & 15;
    const int tid = threadIdx.x;
    const int n = tid & 7;
    const int g = tid >> 3;                // 0..15
    const int nk = n * 16 + k;

    __shared__ __align__(16) float xt[16][264];

    for (int j = tid; j < 16 * 264; j += 128) {
        int ic = j / 264, jj = j - ic * 264;
        int s = sc - 4 + jj;
        xt[ic][jj] = (s >= 0 && s < 4096) ? g_xc[(n0k * 16 + ic) * 4096 + s] : 0.f;
    }

    float w[144];
    #pragma unroll
    for (int i = 0; i < 144; i++) w[i] = g_Weff[nk * 144 + i];
    const float bv = g_beff[nk];
    __syncthreads();

    float acc[16];
    #pragma unroll
    for (int t = 0; t < 16; t++) acc[t] = bv;
    const int sb = g * 16;

    #pragma unroll
    for (int ic = 0; ic < 16; ic++) {
        float xv[24];
        #pragma unroll
        for (int q = 0; q < 6; q++) {
            float4 v = *reinterpret_cast<const float4*>(&xt[ic][sb + q * 4]);
            xv[q * 4 + 0] = v.x; xv[q * 4 + 1] = v.y;
            xv[q * 4 + 2] = v.z; xv[q * 4 + 3] = v.w;
        }
        #pragma unroll
        for (int dk = 0; dk < 9; dk++) {
            float wv = w[ic * 9 + dk];
            #pragma unroll
            for (int t = 0; t < 16; t++)
                acc[t] = fmaf(wv, xv[t + dk], acc[t]);
        }
    }

    float* orow = &g_s0[(((n0k >> 4) * 128) + k * 8 + n) * 4096 + sc + sb];
    #pragma unroll
    for (int q = 0; q < 4; q++)
        *reinterpret_cast<float4*>(&orow[q * 4]) =
            make_float4(acc[q * 4], acc[q * 4 + 1], acc[q * 4 + 2], acc[q * 4 + 3]);
}

// ---------------------------------------------------------------------------
// K4: squash iterations. one block per (n0,k,n) = bid; reads s0 row + U row.
// ---------------------------------------------------------------------------
__device__ __forceinline__ float block_reduce(float p, float* red, int tid) {
    #pragma unroll
    for (int o = 16; o > 0; o >>= 1)
        p += __shfl_xor_sync(0xffffffffu, p, o);
    __syncthreads();
    if ((tid & 31) == 0) red[tid >> 5] = p;
    __syncthreads();
    if (tid == 0) {
        float s = 0.f;
        #pragma unroll
        for (int i = 0; i < 8; i++) s += red[i];
        red[8] = s;
    }
    __syncthreads();
    return red[8];
}

__global__ __launch_bounds__(256) void k_squash(float* __restrict__ out) {
    const int bid = blockIdx.x;            // n0*128 + k*8 + n
    const int kn2 = bid & 127;             // k*8+n
    const int tid = threadIdx.x;

    __shared__ __align__(16) float s0s[4096];
    __shared__ __align__(16) float Us[4096];
    __shared__ float red[9];

    const float4* s0g = reinterpret_cast<const float4*>(&g_s0[bid * 4096]);
    const float4* Ug  = reinterpret_cast<const float4*>(&g_U[kn2 * 4096]);
    for (int i = tid; i < 1024; i += 256) {
        *reinterpret_cast<float4*>(&s0s[i * 4]) = s0g[i];
        *reinterpret_cast<float4*>(&Us[i * 4])  = Ug[i];
    }
    __syncthreads();

    float p, SS;

    // SS0
    p = 0.f;
    for (int s = tid; s < 4096; s += 256) { float v = s0s[s]; p = fmaf(v, v, p); }
    SS = block_reduce(p, red, tid);
    const float f0 = sqrtf(SS) / (1.f + SS);

    // SS1
    p = 0.f;
    for (int s = tid; s < 4096; s += 256) {
        float a = s0s[s], Uv = Us[s];
        float s1 = a * (1.f + f0 * a * Uv);
        p = fmaf(s1, s1, p);
    }
    SS = block_reduce(p, red, tid);
    const float f1 = sqrtf(SS) / (1.f + SS);

    // SS2
    p = 0.f;
    for (int s = tid; s < 4096; s += 256) {
        float a = s0s[s], Uv = Us[s];
        float s1 = a * (1.f + f0 * a * Uv);
        float s2 = a + f1 * s1 * s1 * Uv;
        p = fmaf(s2, s2, p);
    }
    SS = block_reduce(p, red, tid);
    const float f2 = sqrtf(SS) / (1.f + SS);

    float* orow = out + bid * 4096;
    for (int s = tid; s < 4096; s += 256) {
        float a = s0s[s], Uv = Us[s];
        float s1 = a * (1.f + f0 * a * Uv);
        float s2 = a + f1 * s1 * s1 * Uv;
        orow[s] = f2 * s2;
    }
}

// ---------------------------------------------------------------------------
extern "C" void kernel_launch(void* const* d_in, const int* in_sizes, int n_in,
                              void* d_out, int out_size) {
    const float* x      = (const float*)d_in[0];
    const float* conv_w = (const float*)d_in[1];
    const float* conv_b = (const float*)d_in[2];
    const float* caps_w = (const float*)d_in[3];
    const float* caps_b = (const float*)d_in[4];
    const float* W      = (const float*)d_in[5];
    float* out = (float*)d_out;

    k_setup<<<1, 128>>>(W, caps_w, conv_b, caps_b);
    k_weff<<<128, 160>>>(caps_w, conv_w);
    k_xc<<<dim3(16, 8), 128>>>(x);
    k_ucalc<<<dim3(16, 16), 128>>>();
    k_s0conv<<<dim3(16, 128), 128>>>();
    k_squash<<<1024, 256>>>(out);
}